// round 1
// baseline (speedup 1.0000x reference)
#include <cuda_runtime.h>
#include <cuda_bf16.h>

// Problem constants
#define BB   32
#define NN   16384
#define DD   64
#define KK   64

#define CTAS_PER_BATCH 8
#define NCTA (BB * CTAS_PER_BATCH)      // 256 CTAs
#define NT   512                         // threads per CTA
#define PTS  (NN / CTAS_PER_BATCH)       // 2048 points per CTA
#define TILE 128                         // points staged per tile
#define NTILES (PTS / TILE)              // 16
#define TROW 129                         // padded SMEM row stride (bank-conflict avoidance)

// ---------------- device globals (scratch; no allocation allowed) ----------
__device__ unsigned long long g_slot[BB * KK];   // per (batch, round) packed argmax
__device__ unsigned int g_count = 0;             // barrier arrival counter
__device__ unsigned int g_gen   = 0;             // barrier generation (monotonic across replays)

// Software grid barrier. Safe iff all NCTA CTAs are co-resident, which the
// launch_bounds + smem budget below guarantee (2 CTAs/SM * 148+ SMs >= 256).
__device__ __forceinline__ void grid_sync() {
    __syncthreads();
    if (threadIdx.x == 0) {
        __threadfence();                                    // publish my writes
        unsigned int gen = *(volatile unsigned int*)&g_gen;
        unsigned int prev = atomicAdd(&g_count, 1u);
        if (prev == NCTA - 1) {
            g_count = 0;                                    // only last arriver touches
            __threadfence();
            *(volatile unsigned int*)&g_gen = gen + 1;      // release
        } else {
            while (*(volatile unsigned int*)&g_gen == gen) { __nanosleep(64); }
        }
        __threadfence();                                    // acquire others' writes
    }
    __syncthreads();
}

__global__ void __launch_bounds__(NT, 2)
kmpp_kernel(const float* __restrict__ data,
            const int*   __restrict__ first_idx,
            float*       __restrict__ out)
{
    __shared__ float s_tile[DD * TROW];      // 33024 B : transposed point tile [dim][pt]
    __shared__ float s_part[4 * TILE];       //  2048 B : partial dim-group sums
    __shared__ float s_min [PTS];            //  8192 B : running min squared distance
    __shared__ float s_center[DD];           //   256 B
    __shared__ unsigned long long s_red[NT / 32]; // 128 B : per-warp argmax
    __shared__ int s_widx;

    const int t      = threadIdx.x;
    const int cta    = blockIdx.x;
    const int batch  = cta / CTAS_PER_BATCH;
    const int chunk  = cta % CTAS_PER_BATCH;
    const int pbase  = chunk * PTS;
    const float* bd  = data + (size_t)batch * NN * DD;
    float* bout      = out  + (size_t)batch * KK * DD;
    const bool leader = (chunk == 0);

    // Reset this run's argmax slots (deterministic across graph replays).
    if (t < KK * BB / NCTA)                  // 8 slots per CTA
        g_slot[cta * (KK * BB / NCTA) + t] = 0ULL;

    // min_d starts at +inf; round 1's "update" then computes initial distances.
    for (int i = t; i < PTS; i += NT) s_min[i] = 3.4e38f;

    // Center 0 from first_idx.
    {
        int idx0 = first_idx[batch];
        if (t < DD) {
            float c = bd[(size_t)idx0 * DD + t];
            s_center[t] = c;
            if (leader) bout[t] = c;
        }
    }
    grid_sync();   // slot resets + s_center/s_min visible before any atomicMax

    for (int k = 1; k < KK; ++k) {
        // ---- update min_d against current center (center k-1) ----
        for (int tile = 0; tile < NTILES; ++tile) {
            const float4* src = (const float4*)(bd + (size_t)(pbase + tile * TILE) * DD);
            #pragma unroll
            for (int r = 0; r < (TILE * DD / 4) / NT; ++r) {   // 4 coalesced float4 loads
                int idx = r * NT + t;                          // 0..2047
                int p   = idx >> 4;                            // point within tile
                int dc  = idx & 15;                            // float4 chunk of dims
                float4 v = src[idx];
                int row = dc * 4;
                s_tile[(row + 0) * TROW + p] = v.x;
                s_tile[(row + 1) * TROW + p] = v.y;
                s_tile[(row + 2) * TROW + p] = v.z;
                s_tile[(row + 3) * TROW + p] = v.w;
            }
            __syncthreads();

            // 4 dim-groups x 128 points; stride-1 conflict-free LDS
            int p  = t & (TILE - 1);
            int g  = t >> 7;
            int db = g * 16;
            float acc = 0.f;
            #pragma unroll
            for (int d = 0; d < 16; ++d) {
                float diff = s_tile[(db + d) * TROW + p] - s_center[db + d];
                acc = fmaf(diff, diff, acc);
            }
            s_part[g * TILE + p] = acc;
            __syncthreads();

            if (t < TILE) {
                float s = s_part[t] + s_part[TILE + t] + s_part[2 * TILE + t] + s_part[3 * TILE + t];
                int mi = tile * TILE + t;
                s_min[mi] = fminf(s_min[mi], s);
            }
            __syncthreads();
        }

        // ---- per-batch argmax of min_d (packed: dist bits hi, ~idx lo for min-idx ties) ----
        unsigned long long best = 0ULL;
        #pragma unroll
        for (int r = 0; r < PTS / NT; ++r) {                   // 4 values per thread
            int i = r * NT + t;
            unsigned int vb = __float_as_uint(s_min[i]);       // dist >= 0 -> monotonic bits
            unsigned int gi = (unsigned int)(pbase + i);
            unsigned long long pk = ((unsigned long long)vb << 32) | (unsigned long long)(~gi);
            best = max(best, pk);
        }
        #pragma unroll
        for (int off = 16; off; off >>= 1)
            best = max(best, __shfl_xor_sync(0xffffffffu, best, off));
        if ((t & 31) == 0) s_red[t >> 5] = best;
        __syncthreads();
        if (t < NT / 32) {
            best = s_red[t];
            #pragma unroll
            for (int off = 8; off; off >>= 1)
                best = max(best, __shfl_xor_sync(0xffffu, best, off));
            if (t == 0) atomicMax(&g_slot[batch * KK + k], best);
        }

        grid_sync();   // all CTAs' atomicMax for round k complete

        // ---- fetch winner (atomic read -> L2-coherent, avoids stale L1 line) ----
        if (t == 0) {
            unsigned long long v = atomicAdd(&g_slot[batch * KK + k], 0ULL);
            s_widx = (int)(~(unsigned int)(v & 0xffffffffULL));
        }
        __syncthreads();
        int w = s_widx;
        if (t < DD) {
            float c = bd[(size_t)w * DD + t];
            s_center[t] = c;
            if (leader) bout[k * DD + t] = c;
        }
        __syncthreads();
    }
}

extern "C" void kernel_launch(void* const* d_in, const int* in_sizes, int n_in,
                              void* d_out, int out_size) {
    const float* data      = (const float*)d_in[0];   // (B, N, D) fp32
    const int*   first_idx = (const int*)d_in[1];     // (B,) int32
    float*       out       = (float*)d_out;           // (B, K, D) fp32
    (void)in_sizes; (void)n_in; (void)out_size;
    kmpp_kernel<<<NCTA, NT>>>(data, first_idx, out);
}